// round 17
// baseline (speedup 1.0000x reference)
#include <cuda_runtime.h>
#include <cuda_fp16.h>
#include <math.h>
#include <stdint.h>

#define B_ 8
#define N_ 2048
#define H_ 1024
#define E_ 64
#define NT 32            // number of 64-row tiles per batch
#define CHUNK 8          // j-tiles (64 cols each) per partial block
#define MAXC 4           // max chunks per row-tile = ceil(32/8)
#define BLK_PER_B 80     // sum_t ceil((32-t)/8)
// Softmax scale folded into K: 1/sqrt(64) * log2(e).
#define KSCL 0.1803368801111244f

// Scratch (no allocation allowed in kernel_launch).
__device__ __half g_pOh[B_ * NT * MAXC * 64 * 64];   // unnormalized partial O (fp16)
__device__ float g_pm[B_ * NT * MAXC * 64];          // row max (log2e-scaled domain)
__device__ float g_pl[B_ * NT * MAXC * 64];
// K (pre-scaled by KSCL) and V stored fp16.
__device__ __half g_kh[B_ * N_ * E_];
__device__ __half g_vh[B_ * N_ * E_];
// Pre-transposed fp16 weight matrix Bt[n][k] = fp16([Wk|Wv][k][n]).
__device__ __half g_Wh[128 * 1024];

// ---------------------------------------------------------------------------
// Helpers (base-ISA: ldmatrix + mma.sync + cp.async — plain sm_100 target)
// ---------------------------------------------------------------------------
__device__ __forceinline__ uint32_t smem_u32(const void* p) {
    uint32_t a;
    asm("{ .reg .u64 t; cvta.to.shared.u64 t, %1; cvt.u32.u64 %0, t; }"
        : "=r"(a) : "l"(p));
    return a;
}

#define SW128(o) ((o) ^ ((((uint32_t)(o)) >> 3) & 0x70))

#define LDSM_X4(r0, r1, r2, r3, addr) \
    asm volatile("ldmatrix.sync.aligned.m8n8.x4.shared.b16 {%0,%1,%2,%3}, [%4];" \
                 : "=r"(r0), "=r"(r1), "=r"(r2), "=r"(r3) : "r"(addr))

#define LDSM_X4_T(r0, r1, r2, r3, addr) \
    asm volatile("ldmatrix.sync.aligned.m8n8.x4.trans.shared.b16 {%0,%1,%2,%3}, [%4];" \
                 : "=r"(r0), "=r"(r1), "=r"(r2), "=r"(r3) : "r"(addr))

#define MMA_F16(d0, d1, d2, d3, a0, a1, a2, a3, b0, b1) \
    asm volatile("mma.sync.aligned.m16n8k16.row.col.f32.f16.f16.f32 " \
                 "{%0,%1,%2,%3}, {%4,%5,%6,%7}, {%8,%9}, {%0,%1,%2,%3};" \
                 : "+f"(d0), "+f"(d1), "+f"(d2), "+f"(d3) \
                 : "r"(a0), "r"(a1), "r"(a2), "r"(a3), "r"(b0), "r"(b1))

#define CP16(dst, src) \
    asm volatile("cp.async.cg.shared.global [%0], [%1], 16;" \
                 :: "r"(dst), "l"(src) : "memory")
#define CP_COMMIT asm volatile("cp.async.commit_group;" ::: "memory")
#define CP_WAIT(n) asm volatile("cp.async.wait_group %0;" :: "n"(n) : "memory")

__device__ __forceinline__ uint32_t pack2h(float a, float b) {
    __half2 h = __floats2half2_rn(a, b);
    return *reinterpret_cast<uint32_t*>(&h);
}
__device__ __forceinline__ float2 unpack2h(uint32_t u) {
    __half2 h = *reinterpret_cast<__half2*>(&u);
    return __half22float2(h);
}

// ---------------------------------------------------------------------------
// prep_w: Bt[n][k] = fp16(W[k][n]) via coalesced smem transpose.
// ---------------------------------------------------------------------------
__global__ __launch_bounds__(256) void prep_w(const float* __restrict__ Wk,
                                              const float* __restrict__ Wv)
{
    __shared__ float tile[64][65];
    const int tid = threadIdx.x;
    const int mat = blockIdx.x >> 4;
    const int kt  = blockIdx.x & 15;
    const float* W = mat ? Wv : Wk;

#pragma unroll
    for (int l = 0; l < 16; ++l) {
        int i = tid + l * 256;
        int kk = i >> 6;
        int n  = i & 63;
        tile[kk][n] = W[(size_t)(kt * 64 + kk) * E_ + n];
    }
    __syncthreads();

    const int n  = tid >> 2;
    const int k0 = (tid & 3) * 16;
    __half tmp[16];
#pragma unroll
    for (int k = 0; k < 16; ++k)
        tmp[k] = __float2half_rn(tile[k0 + k][n]);
    uint4* dst = reinterpret_cast<uint4*>(
        &g_Wh[(size_t)(mat * 64 + n) * H_ + kt * 64 + k0]);
    dst[0] = reinterpret_cast<uint4*>(tmp)[0];
    dst[1] = reinterpret_cast<uint4*>(tmp)[1];
}

// ---------------------------------------------------------------------------
// proj_mma: C[16384,128] = A @ Bt^T, single-pass fp16, double-buffered.
// BM=64: grid 256, one wave at 2 blocks/SM (48KB smem). 8 warps, warp tile
// 16 rows x 64 cols. Keys pre-scaled by KSCL.
// Per buffer: AH 8KB (64 rows x 128B) + WH 16KB.
// ---------------------------------------------------------------------------
#define OFF_AH 0
#define OFF_WH 8192
#define PBUF   24576
#define PROJ_SMEM (2 * PBUF)

__device__ __forceinline__ void proj_cp_w(uint32_t sb, uint32_t bufoff,
                                          int kt, int tid)
{
#pragma unroll
    for (int l = 0; l < 4; ++l) {      // 1024 16B-chunks: full 128 n-rows
        int idx = tid + l * 256;
        int row = idx >> 3;            // n 0..127
        int s8  = (idx & 7) << 3;      // k-offset 0..56
        uint32_t so = SW128((uint32_t)(row * 128 + s8 * 2));
        CP16(sb + bufoff + OFF_WH + so, &g_Wh[row * H_ + kt * 64 + s8]);
    }
}

__device__ __forceinline__ void proj_load_a(const float* __restrict__ A,
                                            int M0, int kt, int tid, float4* ar)
{
#pragma unroll
    for (int l = 0; l < 4; ++l) {      // 1024 float4 = 64 rows x 64 fp32
        int idx = tid + l * 256;
        int row = idx >> 4;            // 0..63
        int c4  = (idx & 15) << 2;
        ar[l] = *reinterpret_cast<const float4*>(
            A + (size_t)(M0 + row) * H_ + kt * 64 + c4);
    }
}

__device__ __forceinline__ void proj_store_a(char* sm, uint32_t bufoff,
                                             int tid, const float4* ar)
{
#pragma unroll
    for (int l = 0; l < 4; ++l) {
        int idx = tid + l * 256;
        int row = idx >> 4;
        int c4  = (idx & 15) << 2;
        float4 a = ar[l];
        uint32_t so = SW128((uint32_t)(row * 128 + c4 * 2));
        *reinterpret_cast<uint2*>(sm + bufoff + OFF_AH + so) =
            make_uint2(pack2h(a.x, a.y), pack2h(a.z, a.w));
    }
}

__global__ __launch_bounds__(256) void proj_mma(const float* __restrict__ A)
{
    extern __shared__ char sm[];
    const uint32_t sb = smem_u32(sm);
    const int tid = threadIdx.x;
    const int wid = tid >> 5;
    const int lane = tid & 31;
    const int M0 = blockIdx.x * 64;

    const int wm0 = (wid & 3) * 16;    // warp row offset (16 rows)
    const int wn0 = (wid >> 2) * 64;   // 0 -> keys, 64 -> vals

    float acc[8][4];
#pragma unroll
    for (int ni = 0; ni < 8; ++ni)
#pragma unroll
        for (int q = 0; q < 4; ++q) acc[ni][q] = 0.f;

    const int lrow = lane & 15;
    const int lchk = lane >> 4;

    float4 areg[4];

    // ---- prologue ----
    proj_cp_w(sb, 0, 0, tid);
    CP_COMMIT;
    proj_load_a(A, M0, 0, tid, areg);
    proj_store_a(sm, 0, tid, areg);
    proj_cp_w(sb, PBUF, 1, tid);
    CP_COMMIT;
    proj_load_a(A, M0, 1, tid, areg);
    CP_WAIT(1);          // W(0) landed
    __syncthreads();

    for (int kt = 0; kt < 16; ++kt) {
        const uint32_t bo = (kt & 1) ? PBUF : 0;

#pragma unroll
        for (int ks = 0; ks < 4; ++ks) {
            uint32_t ah[4];
            {
                uint32_t off = SW128((uint32_t)(
                    (wm0 + lrow) * 128 + (ks * 2 + lchk) * 16));
                LDSM_X4(ah[0], ah[1], ah[2], ah[3], sb + bo + OFF_AH + off);
            }
            uint32_t bh[4][4];
#pragma unroll
            for (int g = 0; g < 4; ++g) {
                uint32_t off = SW128((uint32_t)(
                    (wn0 + g * 16 + lrow) * 128 + (ks * 2 + lchk) * 16));
                LDSM_X4(bh[g][0], bh[g][1], bh[g][2], bh[g][3],
                        sb + bo + OFF_WH + off);
            }
#pragma unroll
            for (int ni = 0; ni < 8; ++ni) {
                const int g = ni >> 1;
                const int s = ni & 1;
                float* d = acc[ni];
                MMA_F16(d[0], d[1], d[2], d[3],
                        ah[0], ah[1], ah[2], ah[3],
                        bh[g][s], bh[g][s + 2]);
            }
        }

        if (kt < 15)
            proj_store_a(sm, (kt & 1) ? 0 : PBUF, tid, areg);
        __syncthreads();

        if (kt < 14) {
            proj_cp_w(sb, bo, kt + 2, tid);
            CP_COMMIT;
            proj_load_a(A, M0, kt + 2, tid, areg);
            CP_WAIT(1);
        } else {
            CP_WAIT(0);
        }
        __syncthreads();
    }

    // ---- epilogue: keys scaled by KSCL; vals plain fp16 ----
    __half* outm = (wn0 == 0) ? g_kh : g_vh;
    const float scl = (wn0 == 0) ? KSCL : 1.0f;
    const int colb = (lane & 3) * 2;
    const int rowb = M0 + wm0 + (lane >> 2);
#pragma unroll
    for (int ni = 0; ni < 8; ++ni) {
        const int col = ni * 8 + colb;
#pragma unroll
        for (int hq = 0; hq < 2; ++hq) {
            const int r = rowb + hq * 8;
            *reinterpret_cast<uint32_t*>(&outm[(size_t)r * E_ + col]) =
                pack2h(acc[ni][hq * 2 + 0] * scl, acc[ni][hq * 2 + 1] * scl);
        }
    }
}

// ---------------------------------------------------------------------------
// attn_partial: S = Kscaled.Vh (exp2-domain scores) ; O = Ph.Vh^T.
// K fragments hoisted; 3-stage V ring, one barrier per j-tile.
// smem: KH (8KB) + 3 x VH (8KB) -> 32KB.
// ---------------------------------------------------------------------------
#define AT_KH 0
#define AT_V0 8192
#define ATTN_SMEM_BYTES 32768

__device__ __forceinline__ void attn_cp_tile(uint32_t sb, uint32_t off,
                                             const __half* __restrict__ src,
                                             size_t gbase, int tid)
{
#pragma unroll
    for (int l = 0; l < 4; ++l) {
        int idx = tid + l * 128;
        int row = idx >> 3;
        int e8  = (idx & 7) << 3;
        uint32_t so = SW128((uint32_t)(row * 128 + e8 * 2));
        CP16(sb + off + so, src + gbase + (size_t)row * E_ + e8);
    }
}

__global__ __launch_bounds__(128) void attn_partial()
{
    extern __shared__ char sm[];
    const uint32_t sb = smem_u32(sm);
    const int tid = threadIdx.x;
    const int wid = tid >> 5;
    const int lane = tid & 31;

    const int b = blockIdx.x / BLK_PER_B;
    int ent = blockIdx.x - b * BLK_PER_B;
    int t = 0, acc0 = 0;
    for (int tt = 0; tt < NT; ++tt) {
        int nc = (NT - tt + CHUNK - 1) / CHUNK;
        if (ent < acc0 + nc) { t = tt; break; }
        acc0 += nc;
    }
    const int chunk = ent - acc0;
    const int j0 = t + chunk * CHUNK;
    const int j1 = min(NT, j0 + CHUNK);

    const int wm0 = wid * 16;
    const int lrow = lane & 15;
    const int lchk = lane >> 4;

    // ---- prologue: K (g0), V(j0) (g1), V(j0+1) (g2 if it exists) ----
    attn_cp_tile(sb, AT_KH, g_kh, ((size_t)b * N_ + t * 64) * E_, tid);
    CP_COMMIT;
    attn_cp_tile(sb, AT_V0, g_vh, ((size_t)b * N_ + j0 * 64) * E_, tid);
    CP_COMMIT;
    const bool have2 = (j0 + 1 < j1);
    if (have2) {
        attn_cp_tile(sb, AT_V0 + 8192, g_vh,
                     ((size_t)b * N_ + (j0 + 1) * 64) * E_, tid);
        CP_COMMIT;
    }

    // ---- hoist K fragments ----
    if (have2) CP_WAIT(2); else CP_WAIT(1);
    __syncthreads();
    uint32_t kfr[4][4];
#pragma unroll
    for (int ks = 0; ks < 4; ++ks) {
        uint32_t offa = SW128((uint32_t)(
            (wm0 + lrow) * 128 + (ks * 2 + lchk) * 16));
        LDSM_X4(kfr[ks][0], kfr[ks][1], kfr[ks][2], kfr[ks][3], sb + AT_KH + offa);
    }

    float m_i[2], l_i[2], accO[8][4];
#pragma unroll
    for (int h = 0; h < 2; ++h) { m_i[h] = -INFINITY; l_i[h] = 0.f; }
#pragma unroll
    for (int ne = 0; ne < 8; ++ne)
#pragma unroll
        for (int q = 0; q < 4; ++q) accO[ne][q] = 0.f;

    int vslot = 0;
    for (int jt = j0; jt < j1; ++jt) {
        if (jt + 1 < j1) CP_WAIT(1); else CP_WAIT(0);
        __syncthreads();

        if (jt + 2 < j1) {
            int ps = vslot + 2; if (ps >= 3) ps -= 3;
            attn_cp_tile(sb, AT_V0 + ps * 8192, g_vh,
                         ((size_t)b * N_ + (jt + 2) * 64) * E_, tid);
            CP_COMMIT;
        }
        const uint32_t vb = AT_V0 + vslot * 8192;

        // ---- S-gemm ----
        float Sa[8][4];
#pragma unroll
        for (int ni = 0; ni < 8; ++ni)
#pragma unroll
            for (int q = 0; q < 4; ++q) Sa[ni][q] = 0.f;

#pragma unroll
        for (int ks = 0; ks < 4; ++ks) {
            uint32_t bh[4][4];
#pragma unroll
            for (int g = 0; g < 4; ++g) {
                uint32_t offb = SW128((uint32_t)(
                    (g * 16 + lrow) * 128 + (ks * 2 + lchk) * 16));
                LDSM_X4(bh[g][0], bh[g][1], bh[g][2], bh[g][3], sb + vb + offb);
            }
#pragma unroll
            for (int ni = 0; ni < 8; ++ni) {
                const int g = ni >> 1;
                const int s = ni & 1;
                float* d = Sa[ni];
                MMA_F16(d[0], d[1], d[2], d[3],
                        kfr[ks][0], kfr[ks][1], kfr[ks][2], kfr[ks][3],
                        bh[g][s], bh[g][s + 2]);
            }
        }

        // ---- mask (diagonal tile only) ----
        if (jt == t) {
#pragma unroll
            for (int ni = 0; ni < 8; ++ni)
#pragma unroll
                for (int q = 0; q < 4; ++q) {
                    int i_loc = wm0 + (lane >> 2) + ((q >> 1) << 3);
                    int j_loc = ni * 8 + (lane & 3) * 2 + (q & 1);
                    if (j_loc < i_loc) Sa[ni][q] = -1e30f;
                }
        }

        // ---- online softmax (exp2 domain) ----
#pragma unroll
        for (int h = 0; h < 2; ++h) {
            float tmax = -INFINITY;
#pragma unroll
            for (int ni = 0; ni < 8; ++ni)
                tmax = fmaxf(tmax, fmaxf(Sa[ni][h * 2], Sa[ni][h * 2 + 1]));
            tmax = fmaxf(tmax, __shfl_xor_sync(0xffffffffu, tmax, 1));
            tmax = fmaxf(tmax, __shfl_xor_sync(0xffffffffu, tmax, 2));
            float mnew = fmaxf(m_i[h], tmax);
            float alpha = exp2f(m_i[h] - mnew);
            float ps = 0.f;
#pragma unroll
            for (int ni = 0; ni < 8; ++ni) {
                float p0 = exp2f(Sa[ni][h * 2] - mnew);
                float p1 = exp2f(Sa[ni][h * 2 + 1] - mnew);
                Sa[ni][h * 2] = p0;
                Sa[ni][h * 2 + 1] = p1;
                ps += p0 + p1;
            }
            ps += __shfl_xor_sync(0xffffffffu, ps, 1);
            ps += __shfl_xor_sync(0xffffffffu, ps, 2);
            l_i[h] = l_i[h] * alpha + ps;
            m_i[h] = mnew;
#pragma unroll
            for (int ne = 0; ne < 8; ++ne) {
                accO[ne][h * 2] *= alpha;
                accO[ne][h * 2 + 1] *= alpha;
            }
        }

        // ---- O-gemm ----
#pragma unroll
        for (int kc = 0; kc < 4; ++kc) {
            const int n0 = 2 * kc, n1 = 2 * kc + 1;
            uint32_t pah[4];
            pah[0] = pack2h(Sa[n0][0], Sa[n0][1]);
            pah[1] = pack2h(Sa[n0][2], Sa[n0][3]);
            pah[2] = pack2h(Sa[n1][0], Sa[n1][1]);
            pah[3] = pack2h(Sa[n1][2], Sa[n1][3]);
            uint32_t tbh[4][4];
#pragma unroll
            for (int g = 0; g < 4; ++g) {
                uint32_t offt = SW128((uint32_t)(
                    (kc * 16 + lrow) * 128 + g * 32 + lchk * 16));
                LDSM_X4_T(tbh[g][0], tbh[g][1], tbh[g][2], tbh[g][3],
                          sb + vb + offt);
            }
#pragma unroll
            for (int ne = 0; ne < 8; ++ne) {
                const int g = ne >> 1;
                const int s = ne & 1;
                float* d = accO[ne];
                MMA_F16(d[0], d[1], d[2], d[3], pah[0], pah[1], pah[2], pah[3],
                        tbh[g][2 * s], tbh[g][2 * s + 1]);
            }
        }

        vslot = (vslot + 1 == 3) ? 0 : vslot + 1;
    }

    // ---- write unnormalized partials (fp16) ----
    const size_t base = ((size_t)b * NT + t) * MAXC + chunk;
    __half* pO = g_pOh + base * 4096;
    const int r0 = wm0 + (lane >> 2);
    if ((lane & 3) == 0) {
        g_pm[base * 64 + r0]     = m_i[0];
        g_pm[base * 64 + r0 + 8] = m_i[1];
        g_pl[base * 64 + r0]     = l_i[0];
        g_pl[base * 64 + r0 + 8] = l_i[1];
    }
#pragma unroll
    for (int ne = 0; ne < 8; ++ne) {
        const int e = ne * 8 + (lane & 3) * 2;
        *reinterpret_cast<uint32_t*>(&pO[(size_t)r0 * 64 + e]) =
            pack2h(accO[ne][0], accO[ne][1]);
        *reinterpret_cast<uint32_t*>(&pO[(size_t)(r0 + 8) * 64 + e]) =
            pack2h(accO[ne][2], accO[ne][3]);
    }
}

// ---------------------------------------------------------------------------
// Combine (512 blocks, uint4 batched loads), exp2 domain merge.
// ---------------------------------------------------------------------------
__global__ __launch_bounds__(256) void combine_kernel(float* __restrict__ out)
{
    const int half = blockIdx.x & 1;
    const int bt = blockIdx.x >> 1;
    const int t = bt >> 3;
    const int b = bt & 7;
    const int nc = (NT - t + CHUNK - 1) / CHUNK;
    const int tid = threadIdx.x;
    const int r  = tid >> 2;
    const int e0 = half * 32 + (tid & 3) * 8;

    const size_t base = ((size_t)b * NT + t) * MAXC;

    float pm[MAXC], pl[MAXC];
#pragma unroll
    for (int c = 0; c < MAXC; ++c) {
        if (c < nc) {
            pm[c] = g_pm[(base + c) * 64 + r];
            pl[c] = g_pl[(base + c) * 64 + r];
        } else { pm[c] = -INFINITY; pl[c] = 0.f; }
    }
    uint4 raw[MAXC];
#pragma unroll
    for (int c = 0; c < MAXC; ++c) {
        if (c < nc)
            raw[c] = *reinterpret_cast<const uint4*>(
                g_pOh + (base + c) * 4096 + (size_t)r * 64 + e0);
    }

    float m = -INFINITY;
#pragma unroll
    for (int c = 0; c < MAXC; ++c) m = fmaxf(m, pm[c]);

    float w[MAXC], lsum = 0.f;
#pragma unroll
    for (int c = 0; c < MAXC; ++c) {
        float wc = exp2f(pm[c] - m);
        w[c] = wc;
        lsum += wc * pl[c];
    }
    const float inv = 1.f / lsum;

    float o[8];
#pragma unroll
    for (int k = 0; k < 8; ++k) o[k] = 0.f;
#pragma unroll
    for (int c = 0; c < MAXC; ++c) {
        if (c < nc) {
            float wc = w[c];
            float2 p0 = unpack2h(raw[c].x);
            float2 p1 = unpack2h(raw[c].y);
            float2 p2 = unpack2h(raw[c].z);
            float2 p3 = unpack2h(raw[c].w);
            o[0] = fmaf(wc, p0.x, o[0]);
            o[1] = fmaf(wc, p0.y, o[1]);
            o[2] = fmaf(wc, p1.x, o[2]);
            o[3] = fmaf(wc, p1.y, o[3]);
            o[4] = fmaf(wc, p2.x, o[4]);
            o[5] = fmaf(wc, p2.y, o[5]);
            o[6] = fmaf(wc, p3.x, o[6]);
            o[7] = fmaf(wc, p3.y, o[7]);
        }
    }

    float* dst = out + ((size_t)b * N_ + t * 64 + r) * E_ + e0;
    *reinterpret_cast<float4*>(dst) =
        make_float4(o[0] * inv, o[1] * inv, o[2] * inv, o[3] * inv);
    *reinterpret_cast<float4*>(dst + 4) =
        make_float4(o[4] * inv, o[5] * inv, o[6] * inv, o[7] * inv);
}

// ---------------------------------------------------------------------------
extern "C" void kernel_launch(void* const* d_in, const int* in_sizes, int n_in,
                              void* d_out, int out_size)
{
    (void)in_sizes; (void)n_in; (void)out_size;
    const float* input = (const float*)d_in[0];
    const float* Wk    = (const float*)d_in[1];
    // d_in[2] is q — dead in the reference, intentionally unused.
    const float* Wv    = (const float*)d_in[3];
    float* out = (float*)d_out;

    cudaFuncSetAttribute(proj_mma,
                         cudaFuncAttributeMaxDynamicSharedMemorySize, PROJ_SMEM);
    cudaFuncSetAttribute(attn_partial,
                         cudaFuncAttributeMaxDynamicSharedMemorySize, ATTN_SMEM_BYTES);

    prep_w<<<32, 256>>>(Wk, Wv);
    proj_mma<<<256, 256, PROJ_SMEM>>>(input);
    attn_partial<<<B_ * BLK_PER_B, 128, ATTN_SMEM_BYTES>>>();
    combine_kernel<<<B_ * NT * 2, 256>>>(out);
}